// round 9
// baseline (speedup 1.0000x reference)
#include <cuda_runtime.h>
#include <cuda_bf16.h>
#include <cstdint>
#include <math.h>

#define BB 2
#define SS 2048
#define DD 2048
#define HH 16
#define FF 128
#define EPSV 1e-6f

// q prescale: (1/sqrt(128)) * log2(e)  -> scores already in log2 units
#define QSCALE 0.1275174431f
// fixed softmax offset in log2 units; |score_log2| <= 128/sqrt(128)*log2e = 16.33
#define SOFF 16.5f

// ---------------- scratch (static device memory; no allocations) ----------------
__device__ float g_q[4096 * 2048];
__device__ float g_k[4096 * 2048];
__device__ float g_v[4096 * 2048];
__device__ float g_cos[2048 * 64];
__device__ float g_sin[2048 * 64];
// x inputs pre-split: [row 4096][kpair 1024]
__device__ uint32_t g_xqhi[4096 * 1024];
__device__ uint32_t g_xqlo[4096 * 1024];
__device__ uint32_t g_xkhi[4096 * 1024];
__device__ uint32_t g_xklo[4096 * 1024];
__device__ uint32_t g_xvhi[4096 * 1024];
__device__ uint32_t g_xvlo[4096 * 1024];
// split weights, n-major: [n 2048][kpair 1024]
__device__ uint32_t g_w0hi[2048 * 1024];
__device__ uint32_t g_w0lo[2048 * 1024];
__device__ uint32_t g_w1hi[2048 * 1024];
__device__ uint32_t g_w1lo[2048 * 1024];
__device__ uint32_t g_w2hi[2048 * 1024];
__device__ uint32_t g_w2lo[2048 * 1024];
__device__ uint32_t g_wohi[2048 * 1024];
__device__ uint32_t g_wolo[2048 * 1024];
// normed q/k split pairs: [row 4096][pair 1024]
__device__ uint32_t g_qhi[4096 * 1024];
__device__ uint32_t g_qlo[4096 * 1024];
__device__ uint32_t g_khi[4096 * 1024];
__device__ uint32_t g_klo[4096 * 1024];
// V transposed split: [b*2048 + h*128 + f][ppair 1024]
__device__ uint32_t g_vthi[2 * 2048 * 1024];
__device__ uint32_t g_vtlo[2 * 2048 * 1024];
// attention output split pairs: [row 4096][hf-pair 1024]
__device__ uint32_t g_ahi[4096 * 1024];
__device__ uint32_t g_alo[4096 * 1024];

// ---------------- helpers ---------------------------------------------------------
__device__ __forceinline__ uint32_t pack2(__nv_bfloat16 a, __nv_bfloat16 b) {
    __nv_bfloat162 h2;
    h2.x = a; h2.y = b;
    return *reinterpret_cast<uint32_t*>(&h2);
}

__device__ __forceinline__ void split_pair(float e0, float e1, uint32_t& hi, uint32_t& lo) {
    __nv_bfloat16 h0 = __float2bfloat16_rn(e0);
    __nv_bfloat16 h1 = __float2bfloat16_rn(e1);
    float l0 = e0 - __bfloat162float(h0);
    float l1 = e1 - __bfloat162float(h1);
    hi = pack2(h0, h1);
    lo = pack2(__float2bfloat16_rn(l0), __float2bfloat16_rn(l1));
}

__device__ __forceinline__ float fexp2(float x) {
    float r;
    asm("ex2.approx.f32 %0, %1;" : "=f"(r) : "f"(x));
    return r;
}

__device__ __forceinline__ void mma16816(float* c, uint32_t a0, uint32_t a1, uint32_t a2,
                                         uint32_t a3, uint32_t b0, uint32_t b1) {
    asm volatile(
        "mma.sync.aligned.m16n8k16.row.col.f32.bf16.bf16.f32 "
        "{%0,%1,%2,%3},{%4,%5,%6,%7},{%8,%9},{%0,%1,%2,%3};\n"
        : "+f"(c[0]), "+f"(c[1]), "+f"(c[2]), "+f"(c[3])
        : "r"(a0), "r"(a1), "r"(a2), "r"(a3), "r"(b0), "r"(b1));
}

__device__ __forceinline__ void ldsm4(uint32_t& r0, uint32_t& r1, uint32_t& r2, uint32_t& r3,
                                      uint32_t addr) {
    asm volatile("ldmatrix.sync.aligned.m8n8.x4.shared.b16 {%0,%1,%2,%3}, [%4];"
                 : "=r"(r0), "=r"(r1), "=r"(r2), "=r"(r3) : "r"(addr));
}

__device__ __forceinline__ void cpa16(uint32_t dst, const void* src) {
    asm volatile("cp.async.cg.shared.global [%0], [%1], 16;\n" :: "r"(dst), "l"(src));
}

// ---------------- RoPE table -----------------------------------------------------
__global__ void rope_table_kernel(float* __restrict__ cosT, float* __restrict__ sinT) {
    int idx = blockIdx.x * 256 + threadIdx.x;
    if (idx >= 2048 * 64) return;
    int p = idx / 64, i = idx % 64;
    float freq = (float)(1.0 / pow(10000.0, (double)i / 64.0));
    float a = (float)p * freq;
    cosT[idx] = (float)cos((double)a);
    sinT[idx] = (float)sin((double)a);
}

// ---------------- pre-split kernels ----------------------------------------------
__global__ void split_rows3_kernel(const float* __restrict__ x0, const float* __restrict__ x1,
                                   const float* __restrict__ x2,
                                   uint32_t* __restrict__ h0, uint32_t* __restrict__ l0,
                                   uint32_t* __restrict__ h1, uint32_t* __restrict__ l1,
                                   uint32_t* __restrict__ h2, uint32_t* __restrict__ l2) {
    int s = blockIdx.z;
    const float* x = (s == 0) ? x0 : (s == 1) ? x1 : x2;
    uint32_t* xh = (s == 0) ? h0 : (s == 1) ? h1 : h2;
    uint32_t* xl = (s == 0) ? l0 : (s == 1) ? l1 : l2;
    int idx = blockIdx.x * 256 + threadIdx.x;
    float2 v = ((const float2*)x)[idx];
    uint32_t hi, lo;
    split_pair(v.x, v.y, hi, lo);
    xh[idx] = hi;
    xl[idx] = lo;
}

// W[h,d,f] -> n-major pairs: out[n=h*128+f][kp=d/2], tiled transpose; z batches 3
__global__ void wsplit3_kernel(const float* __restrict__ W0, const float* __restrict__ W1,
                               const float* __restrict__ W2,
                               uint32_t* __restrict__ h0p, uint32_t* __restrict__ l0p,
                               uint32_t* __restrict__ h1p, uint32_t* __restrict__ l1p,
                               uint32_t* __restrict__ h2p, uint32_t* __restrict__ l2p) {
    int s = blockIdx.z;
    const float* W = (s == 0) ? W0 : (s == 1) ? W1 : W2;
    uint32_t* wh = (s == 0) ? h0p : (s == 1) ? h1p : h2p;
    uint32_t* wl = (s == 0) ? l0p : (s == 1) ? l1p : l2p;
    __shared__ uint32_t th[32][33];
    __shared__ uint32_t tl[32][33];
    int nb = blockIdx.x * 32, kpb = blockIdx.y * 32;
    int tid = threadIdx.x;
#pragma unroll
    for (int i = 0; i < 4; i++) {
        int ni = tid & 31;
        int kpi = (tid >> 5) + i * 8;
        int n = nb + ni, kp = kpb + kpi;
        long a0 = ((long)(n >> 7) * 2048 + 2 * kp) * 128 + (n & 127);
        float a = W[a0];
        float b = W[a0 + 128];
        uint32_t hi, lo;
        split_pair(a, b, hi, lo);
        th[kpi][ni] = hi;
        tl[kpi][ni] = lo;
    }
    __syncthreads();
#pragma unroll
    for (int i = 0; i < 4; i++) {
        int kpo = tid & 31;
        int no = (tid >> 5) + i * 8;
        long dst = (long)(nb + no) * 1024 + kpb + kpo;
        wh[dst] = th[kpo][no];
        wl[dst] = tl[kpo][no];
    }
}

// WO[hf][m] -> m-major pairs: out[m][kp=hf/2]
__global__ void wosplit_kernel(const float* __restrict__ WO,
                               uint32_t* __restrict__ whi, uint32_t* __restrict__ wlo) {
    __shared__ uint32_t th[32][33];
    __shared__ uint32_t tl[32][33];
    int nb = blockIdx.x * 32, kpb = blockIdx.y * 32;
    int tid = threadIdx.x;
#pragma unroll
    for (int i = 0; i < 4; i++) {
        int ni = tid & 31;
        int kpi = (tid >> 5) + i * 8;
        int n = nb + ni, kp = kpb + kpi;
        long a0 = (long)(2 * kp) * 2048 + n;
        float a = WO[a0];
        float b = WO[a0 + 2048];
        uint32_t hi, lo;
        split_pair(a, b, hi, lo);
        th[kpi][ni] = hi;
        tl[kpi][ni] = lo;
    }
    __syncthreads();
#pragma unroll
    for (int i = 0; i < 4; i++) {
        int kpo = tid & 31;
        int no = (tid >> 5) + i * 8;
        long dst = (long)(nb + no) * 1024 + kpb + kpo;
        whi[dst] = th[kpo][no];
        wlo[dst] = tl[kpo][no];
    }
}

// ---------------- pipelined split-bf16 GEMM, ldmatrix fragments ------------------
// C[4096,2048] = A(pairs)[M][1024] @ B(n-major pairs)[N][1024]^T + bias
// A smem [row 128][20], B smem [col 128][20]; kc=32 (16 pairs), 2-stage cp.async.
#define G2_AS_LO 10240
#define G2_BS_HI 20480
#define G2_BS_LO 30720
#define G2_STAGE 40960
#define G2_SMEM  81920

template <int NSET>
__global__ __launch_bounds__(256, 2)
void bgemm2_kernel(const uint32_t* __restrict__ A0hi, const uint32_t* __restrict__ A0lo,
                   const uint32_t* __restrict__ B0hi, const uint32_t* __restrict__ B0lo,
                   float* __restrict__ C0, const float* __restrict__ bias0,
                   const uint32_t* A1hi, const uint32_t* A1lo,
                   const uint32_t* B1hi, const uint32_t* B1lo,
                   float* C1, const float* bias1,
                   const uint32_t* A2hi, const uint32_t* A2lo,
                   const uint32_t* B2hi, const uint32_t* B2lo,
                   float* C2, const float* bias2) {
    extern __shared__ char gsm[];
    const uint32_t smem_base = (uint32_t)__cvta_generic_to_shared(gsm);

    const uint32_t* Ahi = A0hi;
    const uint32_t* Alo = A0lo;
    const uint32_t* Bhi = B0hi;
    const uint32_t* Blo = B0lo;
    float* C = C0;
    const float* bias = bias0;
    if (NSET > 1) {
        int s = blockIdx.z;
        if (s == 1) { Ahi = A1hi; Alo = A1lo; Bhi = B1hi; Blo = B1lo; C = C1; bias = bias1; }
        else if (s == 2) { Ahi = A2hi; Alo = A2lo; Bhi = B2hi; Blo = B2lo; C = C2; bias = bias2; }
    }

    const int tid = threadIdx.x;
    const int lane = tid & 31;
    const int warp = tid >> 5;
    const int wm = (warp >> 2) * 64;
    const int wn = (warp & 3) * 32;
    const int g = lane >> 2;
    const int t4 = lane & 3;
    const int bm = blockIdx.y * 128, bn = blockIdx.x * 128;

    // per-lane ldmatrix row offset (bytes): row = lane&15, chunk = lane>>4
    const uint32_t lm_off = (((lane & 15) * 20) + ((lane >> 4) * 4)) * 4;

    float acc[4][4][4];
#pragma unroll
    for (int i = 0; i < 4; i++)
#pragma unroll
        for (int j = 0; j < 4; j++)
#pragma unroll
            for (int r = 0; r < 4; r++) acc[i][j][r] = 0.f;

    auto prefetch = [&](int t) {
        uint32_t sb = smem_base + (t & 1) * G2_STAGE;
#pragma unroll
        for (int i = 0; i < 2; i++) {
            int c = tid + i * 256;
            int row = c >> 2, q4 = (c & 3) * 4;
            const uint32_t* sh = Ahi + (long)(bm + row) * 1024 + t * 16 + q4;
            const uint32_t* sl = Alo + (long)(bm + row) * 1024 + t * 16 + q4;
            cpa16(sb + (row * 20 + q4) * 4, sh);
            cpa16(sb + G2_AS_LO + (row * 20 + q4) * 4, sl);
        }
#pragma unroll
        for (int i = 0; i < 2; i++) {
            int c = tid + i * 256;
            int col = c >> 2, q4 = (c & 3) * 4;
            const uint32_t* sh = Bhi + (long)(bn + col) * 1024 + t * 16 + q4;
            const uint32_t* sl = Blo + (long)(bn + col) * 1024 + t * 16 + q4;
            cpa16(sb + G2_BS_HI + (col * 20 + q4) * 4, sh);
            cpa16(sb + G2_BS_LO + (col * 20 + q4) * 4, sl);
        }
        asm volatile("cp.async.commit_group;\n" ::: "memory");
    };

    prefetch(0);

    for (int t = 0; t < 64; t++) {
        if (t + 1 < 64) {
            prefetch(t + 1);
            asm volatile("cp.async.wait_group 1;\n" ::: "memory");
        } else {
            asm volatile("cp.async.wait_group 0;\n" ::: "memory");
        }
        __syncthreads();

        uint32_t sb = smem_base + (t & 1) * G2_STAGE;

#pragma unroll
        for (int ks = 0; ks < 2; ks++) {
            uint32_t bh0[4], bh1[4], bl0[4], bl1[4];
#pragma unroll
            for (int ctp = 0; ctp < 2; ctp++) {
                uint32_t ba = sb + G2_BS_HI + ((wn + ctp * 16) * 20 + ks * 8) * 4 + lm_off;
                ldsm4(bh0[2 * ctp], bh0[2 * ctp + 1], bh1[2 * ctp], bh1[2 * ctp + 1], ba);
                ldsm4(bl0[2 * ctp], bl0[2 * ctp + 1], bl1[2 * ctp], bl1[2 * ctp + 1],
                      ba + (G2_BS_LO - G2_BS_HI));
            }
#pragma unroll
            for (int rt = 0; rt < 4; rt++) {
                uint32_t aa = sb + ((wm + rt * 16) * 20 + ks * 8) * 4 + lm_off;
                uint32_t ah0, ah1, ah2, ah3, al0, al1, al2, al3;
                ldsm4(ah0, ah1, ah2, ah3, aa);
                ldsm4(al0, al1, al2, al3, aa + G2_AS_LO);
#pragma unroll
                for (int ct = 0; ct < 4; ct++) {
                    mma16816(acc[rt][ct], ah0, ah1, ah2, ah3, bh0[ct], bh1[ct]);
                    mma16816(acc[rt][ct], ah0, ah1, ah2, ah3, bl0[ct], bl1[ct]);
                    mma16816(acc[rt][ct], al0, al1, al2, al3, bh0[ct], bh1[ct]);
                }
            }
        }
        __syncthreads();
    }

#pragma unroll
    for (int rt = 0; rt < 4; rt++) {
        int row0 = bm + wm + rt * 16 + g;
#pragma unroll
        for (int ct = 0; ct < 4; ct++) {
            int col0 = bn + wn + ct * 8 + 2 * t4;
            float b0 = bias ? bias[col0] : 0.f;
            float b1 = bias ? bias[col0 + 1] : 0.f;
            float2 v0 = make_float2(acc[rt][ct][0] + b0, acc[rt][ct][1] + b1);
            float2 v1 = make_float2(acc[rt][ct][2] + b0, acc[rt][ct][3] + b1);
            *(float2*)(C + (long)row0 * 2048 + col0) = v0;
            *(float2*)(C + (long)(row0 + 8) * 2048 + col0) = v1;
        }
    }
}

// ---------------- fused RMSNorm + RoPE -> split pairs ----------------------------
__global__ void norm_rope_split_kernel(const float* __restrict__ xq, const float* __restrict__ xk,
                                       const float* __restrict__ wq, const float* __restrict__ wk,
                                       const float* __restrict__ cosT, const float* __restrict__ sinT,
                                       uint32_t* __restrict__ qhi, uint32_t* __restrict__ qlo,
                                       uint32_t* __restrict__ khi, uint32_t* __restrict__ klo) {
    int which = blockIdx.y;
    const float* x = which ? xk : xq;
    const float* w = which ? wk : wq;
    uint32_t* ohi = which ? khi : qhi;
    uint32_t* olo = which ? klo : qlo;
    float scale = which ? 1.f : QSCALE;

    long r = blockIdx.x;
    int h = (int)(r & 15);
    long row = r >> 4;
    int p = (int)(row & (SS - 1));
    const float* ptr = x + row * 2048 + h * 128;
    int f = threadIdx.x;

    float v = ptr[f];
    float ss = v * v;
#pragma unroll
    for (int o = 16; o; o >>= 1) ss += __shfl_xor_sync(0xffffffffu, ss, o);
    __shared__ float red[4];
    if ((f & 31) == 0) red[f >> 5] = ss;
    __syncthreads();
    ss = red[0] + red[1] + red[2] + red[3];

    float rms = sqrtf(ss * (1.f / 128.f));
    float sv = v / (rms + EPSV) * w[f];

    __shared__ float sh[128];
    __shared__ float sh2[128];
    sh[f] = sv;
    __syncthreads();

    int i = f & 63;
    float c = cosT[p * 64 + i], s = sinT[p * 64 + i];
    float out = (f < 64) ? (sv * c - sh[f + 64] * s) : (sv * c + sh[f - 64] * s);
    sh2[f] = out * scale;
    __syncthreads();

    if (f < 64) {
        uint32_t hi, lo;
        split_pair(sh2[2 * f], sh2[2 * f + 1], hi, lo);
        long o = row * 1024 + h * 64 + f;
        ohi[o] = hi;
        olo[o] = lo;
    }
}

// ---------------- V transpose + split --------------------------------------------
__global__ void v_tsplit_kernel(const float* __restrict__ v,
                                uint32_t* __restrict__ vthi, uint32_t* __restrict__ vtlo) {
    int b = blockIdx.z, pb = blockIdx.y, cb = blockIdx.x;
    __shared__ float ts[64][65];
    int tid = threadIdx.x;
#pragma unroll
    for (int i = 0; i < 16; i++) {
        int idx = i * 256 + tid;
        int r = idx >> 6, c = idx & 63;
        ts[r][c] = v[(long)(b * 2048 + pb * 64 + r) * 2048 + cb * 64 + c];
    }
    __syncthreads();
#pragma unroll
    for (int i = 0; i < 8; i++) {
        int idx = i * 256 + tid;
        int c = idx >> 5, pp = idx & 31;
        uint32_t hi, lo;
        split_pair(ts[2 * pp][c], ts[2 * pp + 1][c], hi, lo);
        long dst = (long)(b * 2048 + cb * 64 + c) * 1024 + pb * 32 + pp;
        vthi[dst] = hi;
        vtlo[dst] = lo;
    }
}

// ---------------- flash attention (fixed-offset softmax + ldmatrix frags) --------
#define FL_KSLO 17408
#define FL_VSHI 34816
#define FL_VSLO 53248
#define FL_STAGE 71680
#define FL_SMEM  143360

__global__ __launch_bounds__(256, 1)
void flash_kernel(const uint32_t* __restrict__ qhi, const uint32_t* __restrict__ qlo,
                  const uint32_t* __restrict__ khi, const uint32_t* __restrict__ klo,
                  const uint32_t* __restrict__ vthi, const uint32_t* __restrict__ vtlo,
                  uint32_t* __restrict__ ahi, uint32_t* __restrict__ alo) {
    extern __shared__ char fsm[];
    const int tid = threadIdx.x;
    const int lane = tid & 31, warp = tid >> 5;
    const int g = lane >> 2, t4 = lane & 3;
    const int qt = blockIdx.x, bh = blockIdx.y;
    const int b = bh >> 4, h = bh & 15;
    const int wm = warp * 16;
    const long qr0 = (long)b * 2048 + qt * 128;

    const uint32_t smem_base = (uint32_t)__cvta_generic_to_shared(fsm);
    // ldmatrix per-lane offsets (bytes): K stride 68 words, V stride 36 words
    const uint32_t kf_off = (((lane & 15) * 68) + ((lane >> 4) * 4)) * 4;
    const uint32_t vf_off = (((lane & 15) * 36) + ((lane >> 4) * 4)) * 4;

    uint32_t qah[8][4], qal[8][4];
    {
        const uint32_t* qh0 = qhi + (qr0 + wm + g) * 1024 + h * 64;
        const uint32_t* qh8 = qhi + (qr0 + wm + g + 8) * 1024 + h * 64;
        const uint32_t* ql0 = qlo + (qr0 + wm + g) * 1024 + h * 64;
        const uint32_t* ql8 = qlo + (qr0 + wm + g + 8) * 1024 + h * 64;
#pragma unroll
        for (int fs = 0; fs < 8; fs++) {
            qah[fs][0] = qh0[8 * fs + t4];
            qah[fs][1] = qh8[8 * fs + t4];
            qah[fs][2] = qh0[8 * fs + 4 + t4];
            qah[fs][3] = qh8[8 * fs + 4 + t4];
            qal[fs][0] = ql0[8 * fs + t4];
            qal[fs][1] = ql8[8 * fs + t4];
            qal[fs][2] = ql0[8 * fs + 4 + t4];
            qal[fs][3] = ql8[8 * fs + 4 + t4];
        }
    }

    float acc_o[16][4];
#pragma unroll
    for (int nt = 0; nt < 16; nt++)
#pragma unroll
        for (int j = 0; j < 4; j++) acc_o[nt][j] = 0.f;
    float lrow[2] = {0.f, 0.f};

    const uint32_t* khb = khi + ((long)b * 2048) * 1024 + h * 64;
    const uint32_t* klb = klo + ((long)b * 2048) * 1024 + h * 64;
    const uint32_t* vhb = vthi + ((long)b * 2048 + h * 128) * 1024;
    const uint32_t* vlb = vtlo + ((long)b * 2048 + h * 128) * 1024;

    auto prefetch = [&](int kb) {
        uint32_t sb = smem_base + (kb & 1) * FL_STAGE;
        const uint32_t* kh = khb + (long)kb * 64 * 1024;
        const uint32_t* kl = klb + (long)kb * 64 * 1024;
#pragma unroll
        for (int i = 0; i < 4; i++) {
            int c = tid + i * 256;
            int row = c >> 4, cc = (c & 15) * 4;
            cpa16(sb + (row * 68 + cc) * 4, kh + (long)row * 1024 + cc);
            cpa16(sb + FL_KSLO + (row * 68 + cc) * 4, kl + (long)row * 1024 + cc);
        }
#pragma unroll
        for (int i = 0; i < 4; i++) {
            int c = tid + i * 256;
            int col = c >> 3, ci = (c & 7) * 4;
            cpa16(sb + FL_VSHI + (col * 36 + ci) * 4, vhb + (long)col * 1024 + kb * 32 + ci);
            cpa16(sb + FL_VSLO + (col * 36 + ci) * 4, vlb + (long)col * 1024 + kb * 32 + ci);
        }
        asm volatile("cp.async.commit_group;\n" ::: "memory");
    };

    prefetch(0);

    for (int kb = 0; kb < 32; kb++) {
        if (kb + 1 < 32) {
            prefetch(kb + 1);
            asm volatile("cp.async.wait_group 1;\n" ::: "memory");
        } else {
            asm volatile("cp.async.wait_group 0;\n" ::: "memory");
        }
        __syncthreads();

        uint32_t sb = smem_base + (kb & 1) * FL_STAGE;

        // ---- S = Q @ K^T (scores in log2 units via QSCALE) ----
        float sacc[8][4];
#pragma unroll
        for (int nt = 0; nt < 8; nt++)
#pragma unroll
            for (int j = 0; j < 4; j++) sacc[nt][j] = 0.f;

#pragma unroll
        for (int fs = 0; fs < 8; fs++) {
            uint32_t kb0h[8], kb1h[8], kb0l[8], kb1l[8];
#pragma unroll
            for (int nt0 = 0; nt0 < 8; nt0 += 2) {
                uint32_t ka = sb + (nt0 * 8 * 68 + fs * 8) * 4 + kf_off;
                ldsm4(kb0h[nt0], kb0h[nt0 + 1], kb1h[nt0], kb1h[nt0 + 1], ka);
                ldsm4(kb0l[nt0], kb0l[nt0 + 1], kb1l[nt0], kb1l[nt0 + 1], ka + FL_KSLO);
            }
#pragma unroll
            for (int nt = 0; nt < 8; nt++) {
                mma16816(sacc[nt], qah[fs][0], qah[fs][1], qah[fs][2], qah[fs][3], kb0h[nt], kb1h[nt]);
                mma16816(sacc[nt], qah[fs][0], qah[fs][1], qah[fs][2], qah[fs][3], kb0l[nt], kb1l[nt]);
                mma16816(sacc[nt], qal[fs][0], qal[fs][1], qal[fs][2], qal[fs][3], kb0h[nt], kb1h[nt]);
            }
        }

        // ---- fixed-offset softmax: p = 2^(s - SOFF); no max, no rescale ----
#pragma unroll
        for (int r = 0; r < 2; r++) {
            float rs = 0.f;
#pragma unroll
            for (int nt = 0; nt < 8; nt++) {
                float p0 = fexp2(sacc[nt][2 * r] - SOFF);
                float p1 = fexp2(sacc[nt][2 * r + 1] - SOFF);
                sacc[nt][2 * r] = p0;
                sacc[nt][2 * r + 1] = p1;
                rs += p0 + p1;
            }
            rs += __shfl_xor_sync(0xffffffffu, rs, 1);
            rs += __shfl_xor_sync(0xffffffffu, rs, 2);
            lrow[r] += rs;
        }

        // ---- O += P @ V, 3-pass split ----
#pragma unroll
        for (int s = 0; s < 4; s++) {
            uint32_t ph[4], pl[4];
            {
                uint32_t h0, l0;
                split_pair(sacc[2 * s][0], sacc[2 * s][1], h0, l0);         ph[0] = h0; pl[0] = l0;
                split_pair(sacc[2 * s][2], sacc[2 * s][3], h0, l0);         ph[1] = h0; pl[1] = l0;
                split_pair(sacc[2 * s + 1][0], sacc[2 * s + 1][1], h0, l0); ph[2] = h0; pl[2] = l0;
                split_pair(sacc[2 * s + 1][2], sacc[2 * s + 1][3], h0, l0); ph[3] = h0; pl[3] = l0;
            }
#pragma unroll
            for (int nt0 = 0; nt0 < 16; nt0 += 2) {
                uint32_t va = sb + FL_VSHI + (nt0 * 8 * 36 + s * 8) * 4 + vf_off;
                uint32_t v0h0, v0h1, v1h0, v1h1, v0l0, v0l1, v1l0, v1l1;
                ldsm4(v0h0, v0h1, v1h0, v1h1, va);
                ldsm4(v0l0, v0l1, v1l0, v1l1, va + (FL_VSLO - FL_VSHI));
                mma16816(acc_o[nt0], ph[0], ph[1], ph[2], ph[3], v0h0, v1h0);
                mma16816(acc_o[nt0], pl[0], pl[1], pl[2], pl[3], v0h0, v1h0);
                mma16816(acc_o[nt0], ph[0], ph[1], ph[2], ph[3], v0l0, v1l0);
                mma16816(acc_o[nt0 + 1], ph[0], ph[1], ph[2], ph[3], v0h1, v1h1);
                mma16816(acc_o[nt0 + 1], pl[0], pl[1], pl[2], pl[3], v0h1, v1h1);
                mma16816(acc_o[nt0 + 1], ph[0], ph[1], ph[2], ph[3], v0l1, v1l1);
            }
        }
        __syncthreads();
    }

    float inv0 = 1.f / lrow[0];
    float inv1 = 1.f / lrow[1];
    long r0 = (qr0 + wm + g) * 1024 + h * 64;
    long r8 = (qr0 + wm + g + 8) * 1024 + h * 64;
#pragma unroll
    for (int nt = 0; nt < 16; nt++) {
        int pp = nt * 4 + t4;
        uint32_t hi, lo;
        split_pair(acc_o[nt][0] * inv0, acc_o[nt][1] * inv0, hi, lo);
        ahi[r0 + pp] = hi;
        alo[r0 + pp] = lo;
        split_pair(acc_o[nt][2] * inv1, acc_o[nt][3] * inv1, hi, lo);
        ahi[r8 + pp] = hi;
        alo[r8 + pp] = lo;
    }
}

// ---------------- host orchestration ----------------------------------------------
extern "C" void kernel_launch(void* const* d_in, const int* in_sizes, int n_in,
                              void* d_out, int out_size) {
    const float* xq = (const float*)d_in[0];
    const float* xk = (const float*)d_in[1];
    const float* xv = (const float*)d_in[2];
    const float* WQ = (const float*)d_in[3];
    const float* WK = (const float*)d_in[4];
    const float* WV = (const float*)d_in[5];
    const float* WO = (const float*)d_in[6];
    const float* bQ = (const float*)d_in[7];
    const float* bK = (const float*)d_in[8];
    const float* bV = (const float*)d_in[9];
    const float* bO = (const float*)d_in[10];
    const float* qw = (const float*)d_in[11];
    const float* kw = (const float*)d_in[12];
    float* out = (float*)d_out;

    float *qb, *kb, *vb, *ct, *st;
    uint32_t *xqhi, *xqlo, *xkhi, *xklo, *xvhi, *xvlo;
    uint32_t *w0hi, *w0lo, *w1hi, *w1lo, *w2hi, *w2lo, *wohi, *wolo;
    uint32_t *qhi, *qlo, *khi, *klo, *vthi, *vtlo, *ahi, *alo;
    cudaGetSymbolAddress((void**)&qb, g_q);
    cudaGetSymbolAddress((void**)&kb, g_k);
    cudaGetSymbolAddress((void**)&vb, g_v);
    cudaGetSymbolAddress((void**)&ct, g_cos);
    cudaGetSymbolAddress((void**)&st, g_sin);
    cudaGetSymbolAddress((void**)&xqhi, g_xqhi);
    cudaGetSymbolAddress((void**)&xqlo, g_xqlo);
    cudaGetSymbolAddress((void**)&xkhi, g_xkhi);
    cudaGetSymbolAddress((void**)&xklo, g_xklo);
    cudaGetSymbolAddress((void**)&xvhi, g_xvhi);
    cudaGetSymbolAddress((void**)&xvlo, g_xvlo);
    cudaGetSymbolAddress((void**)&w0hi, g_w0hi);
    cudaGetSymbolAddress((void**)&w0lo, g_w0lo);
    cudaGetSymbolAddress((void**)&w1hi, g_w1hi);
    cudaGetSymbolAddress((void**)&w1lo, g_w1lo);
    cudaGetSymbolAddress((void**)&w2hi, g_w2hi);
    cudaGetSymbolAddress((void**)&w2lo, g_w2lo);
    cudaGetSymbolAddress((void**)&wohi, g_wohi);
    cudaGetSymbolAddress((void**)&wolo, g_wolo);
    cudaGetSymbolAddress((void**)&qhi, g_qhi);
    cudaGetSymbolAddress((void**)&qlo, g_qlo);
    cudaGetSymbolAddress((void**)&khi, g_khi);
    cudaGetSymbolAddress((void**)&klo, g_klo);
    cudaGetSymbolAddress((void**)&vthi, g_vthi);
    cudaGetSymbolAddress((void**)&vtlo, g_vtlo);
    cudaGetSymbolAddress((void**)&ahi, g_ahi);
    cudaGetSymbolAddress((void**)&alo, g_alo);

    cudaFuncSetAttribute(flash_kernel, cudaFuncAttributeMaxDynamicSharedMemorySize, FL_SMEM);
    cudaFuncSetAttribute(bgemm2_kernel<3>, cudaFuncAttributeMaxDynamicSharedMemorySize, G2_SMEM);
    cudaFuncSetAttribute(bgemm2_kernel<1>, cudaFuncAttributeMaxDynamicSharedMemorySize, G2_SMEM);

    rope_table_kernel<<<(2048 * 64 + 255) / 256, 256>>>(ct, st);

    // pre-split inputs + weights
    dim3 gS(16384, 1, 3);
    split_rows3_kernel<<<gS, 256>>>(xq, xk, xv, xqhi, xqlo, xkhi, xklo, xvhi, xvlo);
    dim3 gW(64, 32, 3);
    wsplit3_kernel<<<gW, 256>>>(WQ, WK, WV, w0hi, w0lo, w1hi, w1lo, w2hi, w2lo);
    dim3 gWo(64, 32, 1);
    wosplit_kernel<<<gWo, 256>>>(WO, wohi, wolo);

    // QKV projections: one batched launch
    dim3 gProj3(16, 32, 3);
    bgemm2_kernel<3><<<gProj3, 256, G2_SMEM>>>(
        xqhi, xqlo, w0hi, w0lo, qb, bQ,
        xkhi, xklo, w1hi, w1lo, kb, bK,
        xvhi, xvlo, w2hi, w2lo, vb, bV);

    // RMSNorm + RoPE + split (q scaled by QSCALE)
    dim3 gNR(BB * SS * HH, 2);
    norm_rope_split_kernel<<<gNR, 128>>>(qb, kb, qw, kw, ct, st, qhi, qlo, khi, klo);

    // V transpose + split
    dim3 gV(32, 32, 2);
    v_tsplit_kernel<<<gV, 256>>>(vb, vthi, vtlo);

    // flash attention -> split pair output
    dim3 gF(16, 32);
    flash_kernel<<<gF, 256, FL_SMEM>>>(qhi, qlo, khi, klo, vthi, vtlo, ahi, alo);

    // output projection
    dim3 gProj(16, 32, 1);
    bgemm2_kernel<1><<<gProj, 256, G2_SMEM>>>(
        ahi, alo, wohi, wolo, out, bO,
        nullptr, nullptr, nullptr, nullptr, nullptr, nullptr,
        nullptr, nullptr, nullptr, nullptr, nullptr, nullptr);
}

// round 10
// speedup vs baseline: 1.1529x; 1.1529x over previous
#include <cuda_runtime.h>
#include <cuda_bf16.h>
#include <cstdint>
#include <math.h>

#define BB 2
#define SS 2048
#define DD 2048
#define HH 16
#define FF 128
#define EPSV 1e-6f

// q prescale: (1/sqrt(128)) * log2(e)  -> scores already in log2 units
#define QSCALE 0.1275174431f
// fixed softmax offset in log2 units; |score_log2| <= 128/sqrt(128)*log2e = 16.33
#define SOFF 16.5f

// ---------------- scratch (static device memory; no allocations) ----------------
__device__ float g_q[4096 * 2048];
__device__ float g_k[4096 * 2048];
__device__ float g_v[4096 * 2048];
__device__ float g_cos[2048 * 64];
__device__ float g_sin[2048 * 64];
// x inputs pre-split: [row 4096][kpair 1024]
__device__ uint32_t g_xqhi[4096 * 1024];
__device__ uint32_t g_xqlo[4096 * 1024];
__device__ uint32_t g_xkhi[4096 * 1024];
__device__ uint32_t g_xklo[4096 * 1024];
__device__ uint32_t g_xvhi[4096 * 1024];
__device__ uint32_t g_xvlo[4096 * 1024];
// transposed+split weights: [kpair 1024][n 2048]
__device__ uint32_t g_w0hi[1024 * 2048];
__device__ uint32_t g_w0lo[1024 * 2048];
__device__ uint32_t g_w1hi[1024 * 2048];
__device__ uint32_t g_w1lo[1024 * 2048];
__device__ uint32_t g_w2hi[1024 * 2048];
__device__ uint32_t g_w2lo[1024 * 2048];
__device__ uint32_t g_wohi[1024 * 2048];
__device__ uint32_t g_wolo[1024 * 2048];
// normed q/k split pairs: [row 4096][pair 1024]
__device__ uint32_t g_qhi[4096 * 1024];
__device__ uint32_t g_qlo[4096 * 1024];
__device__ uint32_t g_khi[4096 * 1024];
__device__ uint32_t g_klo[4096 * 1024];
// V transposed split: [b*2048 + h*128 + f][ppair 1024]
__device__ uint32_t g_vthi[2 * 2048 * 1024];
__device__ uint32_t g_vtlo[2 * 2048 * 1024];
// flash partials (split-KV): [z 2][row 4096][hf 2048], l sums [z 2][row 4096][h 16]
__device__ float g_part[2 * 4096 * 2048];
__device__ float g_lsum[2 * 4096 * 16];
// attention output split pairs: [row 4096][hf-pair 1024]
__device__ uint32_t g_ahi[4096 * 1024];
__device__ uint32_t g_alo[4096 * 1024];

// ---------------- helpers ---------------------------------------------------------
__device__ __forceinline__ uint32_t pack2(__nv_bfloat16 a, __nv_bfloat16 b) {
    __nv_bfloat162 h2;
    h2.x = a; h2.y = b;
    return *reinterpret_cast<uint32_t*>(&h2);
}

__device__ __forceinline__ void split_pair(float e0, float e1, uint32_t& hi, uint32_t& lo) {
    __nv_bfloat16 h0 = __float2bfloat16_rn(e0);
    __nv_bfloat16 h1 = __float2bfloat16_rn(e1);
    float l0 = e0 - __bfloat162float(h0);
    float l1 = e1 - __bfloat162float(h1);
    hi = pack2(h0, h1);
    lo = pack2(__float2bfloat16_rn(l0), __float2bfloat16_rn(l1));
}

__device__ __forceinline__ float fexp2(float x) {
    float r;
    asm("ex2.approx.f32 %0, %1;" : "=f"(r) : "f"(x));
    return r;
}

__device__ __forceinline__ void mma16816(float* c, uint32_t a0, uint32_t a1, uint32_t a2,
                                         uint32_t a3, uint32_t b0, uint32_t b1) {
    asm volatile(
        "mma.sync.aligned.m16n8k16.row.col.f32.bf16.bf16.f32 "
        "{%0,%1,%2,%3},{%4,%5,%6,%7},{%8,%9},{%0,%1,%2,%3};\n"
        : "+f"(c[0]), "+f"(c[1]), "+f"(c[2]), "+f"(c[3])
        : "r"(a0), "r"(a1), "r"(a2), "r"(a3), "r"(b0), "r"(b1));
}

__device__ __forceinline__ void cpa16(uint32_t dst, const void* src) {
    asm volatile("cp.async.cg.shared.global [%0], [%1], 16;\n" :: "r"(dst), "l"(src));
}

// ---------------- RoPE table -----------------------------------------------------
__global__ void rope_table_kernel(float* __restrict__ cosT, float* __restrict__ sinT) {
    int idx = blockIdx.x * 256 + threadIdx.x;
    if (idx >= 2048 * 64) return;
    int p = idx / 64, i = idx % 64;
    float freq = (float)(1.0 / pow(10000.0, (double)i / 64.0));
    float a = (float)p * freq;
    cosT[idx] = (float)cos((double)a);
    sinT[idx] = (float)sin((double)a);
}

// ---------------- pre-split kernels ----------------------------------------------
__global__ void split_rows3_kernel(const float* __restrict__ x0, const float* __restrict__ x1,
                                   const float* __restrict__ x2,
                                   uint32_t* __restrict__ h0, uint32_t* __restrict__ l0,
                                   uint32_t* __restrict__ h1, uint32_t* __restrict__ l1,
                                   uint32_t* __restrict__ h2, uint32_t* __restrict__ l2) {
    int s = blockIdx.z;
    const float* x = (s == 0) ? x0 : (s == 1) ? x1 : x2;
    uint32_t* xh = (s == 0) ? h0 : (s == 1) ? h1 : h2;
    uint32_t* xl = (s == 0) ? l0 : (s == 1) ? l1 : l2;
    int idx = blockIdx.x * 256 + threadIdx.x;
    float2 v = ((const float2*)x)[idx];
    uint32_t hi, lo;
    split_pair(v.x, v.y, hi, lo);
    xh[idx] = hi;
    xl[idx] = lo;
}

// W[h,d,f] -> pairs over d: [kp=d/2][n=h*128+f]; z batches 3 weights
__global__ void wsplit3_kernel(const float* __restrict__ W0, const float* __restrict__ W1,
                               const float* __restrict__ W2,
                               uint32_t* __restrict__ h0, uint32_t* __restrict__ l0,
                               uint32_t* __restrict__ h1, uint32_t* __restrict__ l1,
                               uint32_t* __restrict__ h2, uint32_t* __restrict__ l2) {
    int s = blockIdx.z;
    const float* W = (s == 0) ? W0 : (s == 1) ? W1 : W2;
    uint32_t* wh = (s == 0) ? h0 : (s == 1) ? h1 : h2;
    uint32_t* wl = (s == 0) ? l0 : (s == 1) ? l1 : l2;
    int idx = blockIdx.x * 256 + threadIdx.x;
    int kp = idx >> 11, n = idx & 2047;
    int h = n >> 7, f = n & 127;
    float a = W[((long)h * 2048 + 2 * kp) * 128 + f];
    float b = W[((long)h * 2048 + 2 * kp + 1) * 128 + f];
    uint32_t hi, lo;
    split_pair(a, b, hi, lo);
    wh[idx] = hi;
    wl[idx] = lo;
}

// WO[hf][m] -> pairs over hf: [kp=hf/2][m]
__global__ void wosplit_kernel(const float* __restrict__ WO,
                               uint32_t* __restrict__ whi, uint32_t* __restrict__ wlo) {
    int idx = blockIdx.x * 256 + threadIdx.x;
    int kp = idx >> 11, m = idx & 2047;
    float a = WO[(long)(2 * kp) * 2048 + m];
    float b = WO[(long)(2 * kp + 1) * 2048 + m];
    uint32_t hi, lo;
    split_pair(a, b, hi, lo);
    whi[idx] = hi;
    wlo[idx] = lo;
}

// ---------------- pipelined split-bf16 GEMM on pre-split pair arrays -------------
#define G2_AS_LO 10240
#define G2_BS_HI 20480
#define G2_BS_LO 29184
#define G2_STAGE 37888
#define G2_SMEM  75776

template <int NSET>
__global__ __launch_bounds__(256, 2)
void bgemm2_kernel(const uint32_t* __restrict__ A0hi, const uint32_t* __restrict__ A0lo,
                   const uint32_t* __restrict__ B0hi, const uint32_t* __restrict__ B0lo,
                   float* __restrict__ C0, const float* __restrict__ bias0,
                   const uint32_t* A1hi, const uint32_t* A1lo,
                   const uint32_t* B1hi, const uint32_t* B1lo,
                   float* C1, const float* bias1,
                   const uint32_t* A2hi, const uint32_t* A2lo,
                   const uint32_t* B2hi, const uint32_t* B2lo,
                   float* C2, const float* bias2) {
    extern __shared__ char gsm[];
    const uint32_t smem_base = (uint32_t)__cvta_generic_to_shared(gsm);

    const uint32_t* Ahi = A0hi;
    const uint32_t* Alo = A0lo;
    const uint32_t* Bhi = B0hi;
    const uint32_t* Blo = B0lo;
    float* C = C0;
    const float* bias = bias0;
    if (NSET > 1) {
        int s = blockIdx.z;
        if (s == 1) { Ahi = A1hi; Alo = A1lo; Bhi = B1hi; Blo = B1lo; C = C1; bias = bias1; }
        else if (s == 2) { Ahi = A2hi; Alo = A2lo; Bhi = B2hi; Blo = B2lo; C = C2; bias = bias2; }
    }

    const int tid = threadIdx.x;
    const int lane = tid & 31;
    const int warp = tid >> 5;
    const int wm = (warp >> 2) * 64;
    const int wn = (warp & 3) * 32;
    const int g = lane >> 2;
    const int t4 = lane & 3;
    const int bm = blockIdx.y * 128, bn = blockIdx.x * 128;

    float acc[4][4][4];
#pragma unroll
    for (int i = 0; i < 4; i++)
#pragma unroll
        for (int j = 0; j < 4; j++)
#pragma unroll
            for (int r = 0; r < 4; r++) acc[i][j][r] = 0.f;

    auto prefetch = [&](int t) {
        uint32_t sb = smem_base + (t & 1) * G2_STAGE;
#pragma unroll
        for (int i = 0; i < 2; i++) {
            int c = tid + i * 256;
            int row = c >> 2, q4 = (c & 3) * 4;
            const uint32_t* sh = Ahi + (long)(bm + row) * 1024 + t * 16 + q4;
            const uint32_t* sl = Alo + (long)(bm + row) * 1024 + t * 16 + q4;
            cpa16(sb + (row * 20 + q4) * 4, sh);
            cpa16(sb + G2_AS_LO + (row * 20 + q4) * 4, sl);
        }
#pragma unroll
        for (int i = 0; i < 2; i++) {
            int c = tid + i * 256;
            int kp = c >> 5, n4 = (c & 31) * 4;
            const uint32_t* sh = Bhi + (long)(t * 16 + kp) * 2048 + bn + n4;
            const uint32_t* sl = Blo + (long)(t * 16 + kp) * 2048 + bn + n4;
            cpa16(sb + G2_BS_HI + (kp * 136 + n4) * 4, sh);
            cpa16(sb + G2_BS_LO + (kp * 136 + n4) * 4, sl);
        }
        asm volatile("cp.async.commit_group;\n" ::: "memory");
    };

    prefetch(0);

    for (int t = 0; t < 64; t++) {
        if (t + 1 < 64) {
            prefetch(t + 1);
            asm volatile("cp.async.wait_group 1;\n" ::: "memory");
        } else {
            asm volatile("cp.async.wait_group 0;\n" ::: "memory");
        }
        __syncthreads();

        const uint32_t* ash = (const uint32_t*)(gsm + (t & 1) * G2_STAGE);
        const uint32_t* asl = (const uint32_t*)(gsm + (t & 1) * G2_STAGE + G2_AS_LO);
        const uint32_t* bsh = (const uint32_t*)(gsm + (t & 1) * G2_STAGE + G2_BS_HI);
        const uint32_t* bsl = (const uint32_t*)(gsm + (t & 1) * G2_STAGE + G2_BS_LO);

#pragma unroll
        for (int ks = 0; ks < 2; ks++) {
            const int kp0 = ks * 8 + t4;
            uint32_t bh0[4], bh1[4], bl0[4], bl1[4];
#pragma unroll
            for (int ct = 0; ct < 4; ct++) {
                int col = wn + ct * 8 + g;
                bh0[ct] = bsh[kp0 * 136 + col];
                bh1[ct] = bsh[(kp0 + 4) * 136 + col];
                bl0[ct] = bsl[kp0 * 136 + col];
                bl1[ct] = bsl[(kp0 + 4) * 136 + col];
            }
#pragma unroll
            for (int rt = 0; rt < 4; rt++) {
                int row = wm + rt * 16 + g;
                uint32_t ah0 = ash[row * 20 + kp0];
                uint32_t ah1 = ash[(row + 8) * 20 + kp0];
                uint32_t ah2 = ash[row * 20 + kp0 + 4];
                uint32_t ah3 = ash[(row + 8) * 20 + kp0 + 4];
                uint32_t al0 = asl[row * 20 + kp0];
                uint32_t al1 = asl[(row + 8) * 20 + kp0];
                uint32_t al2 = asl[row * 20 + kp0 + 4];
                uint32_t al3 = asl[(row + 8) * 20 + kp0 + 4];
#pragma unroll
                for (int ct = 0; ct < 4; ct++) {
                    mma16816(acc[rt][ct], ah0, ah1, ah2, ah3, bh0[ct], bh1[ct]);
                    mma16816(acc[rt][ct], ah0, ah1, ah2, ah3, bl0[ct], bl1[ct]);
                    mma16816(acc[rt][ct], al0, al1, al2, al3, bh0[ct], bh1[ct]);
                }
            }
        }
        __syncthreads();
    }

#pragma unroll
    for (int rt = 0; rt < 4; rt++) {
        int row0 = bm + wm + rt * 16 + g;
#pragma unroll
        for (int ct = 0; ct < 4; ct++) {
            int col0 = bn + wn + ct * 8 + 2 * t4;
            float b0 = bias ? bias[col0] : 0.f;
            float b1 = bias ? bias[col0 + 1] : 0.f;
            float2 v0 = make_float2(acc[rt][ct][0] + b0, acc[rt][ct][1] + b1);
            float2 v1 = make_float2(acc[rt][ct][2] + b0, acc[rt][ct][3] + b1);
            *(float2*)(C + (long)row0 * 2048 + col0) = v0;
            *(float2*)(C + (long)(row0 + 8) * 2048 + col0) = v1;
        }
    }
}

// ---------------- fused RMSNorm + RoPE -> split pairs (q and k in one launch) ----
__global__ void norm_rope_split_kernel(const float* __restrict__ xq, const float* __restrict__ xk,
                                       const float* __restrict__ wq, const float* __restrict__ wk,
                                       const float* __restrict__ cosT, const float* __restrict__ sinT,
                                       uint32_t* __restrict__ qhi, uint32_t* __restrict__ qlo,
                                       uint32_t* __restrict__ khi, uint32_t* __restrict__ klo) {
    int which = blockIdx.y;
    const float* x = which ? xk : xq;
    const float* w = which ? wk : wq;
    uint32_t* ohi = which ? khi : qhi;
    uint32_t* olo = which ? klo : qlo;
    float scale = which ? 1.f : QSCALE;

    long r = blockIdx.x;
    int h = (int)(r & 15);
    long row = r >> 4;
    int p = (int)(row & (SS - 1));
    const float* ptr = x + row * 2048 + h * 128;
    int f = threadIdx.x;

    float v = ptr[f];
    float ss = v * v;
#pragma unroll
    for (int o = 16; o; o >>= 1) ss += __shfl_xor_sync(0xffffffffu, ss, o);
    __shared__ float red[4];
    if ((f & 31) == 0) red[f >> 5] = ss;
    __syncthreads();
    ss = red[0] + red[1] + red[2] + red[3];

    float rms = sqrtf(ss * (1.f / 128.f));
    float sv = v / (rms + EPSV) * w[f];

    __shared__ float sh[128];
    __shared__ float sh2[128];
    sh[f] = sv;
    __syncthreads();

    int i = f & 63;
    float c = cosT[p * 64 + i], s = sinT[p * 64 + i];
    float out = (f < 64) ? (sv * c - sh[f + 64] * s) : (sv * c + sh[f - 64] * s);
    sh2[f] = out * scale;
    __syncthreads();

    if (f < 64) {
        uint32_t hi, lo;
        split_pair(sh2[2 * f], sh2[2 * f + 1], hi, lo);
        long o = row * 1024 + h * 64 + f;
        ohi[o] = hi;
        olo[o] = lo;
    }
}

// ---------------- V transpose + split --------------------------------------------
__global__ void v_tsplit_kernel(const float* __restrict__ v,
                                uint32_t* __restrict__ vthi, uint32_t* __restrict__ vtlo) {
    int b = blockIdx.z, pb = blockIdx.y, cb = blockIdx.x;
    __shared__ float ts[64][65];
    int tid = threadIdx.x;
#pragma unroll
    for (int i = 0; i < 16; i++) {
        int idx = i * 256 + tid;
        int r = idx >> 6, c = idx & 63;
        ts[r][c] = v[(long)(b * 2048 + pb * 64 + r) * 2048 + cb * 64 + c];
    }
    __syncthreads();
#pragma unroll
    for (int i = 0; i < 8; i++) {
        int idx = i * 256 + tid;
        int c = idx >> 5, pp = idx & 31;
        uint32_t hi, lo;
        split_pair(ts[2 * pp][c], ts[2 * pp + 1][c], hi, lo);
        long dst = (long)(b * 2048 + cb * 64 + c) * 1024 + pb * 32 + pp;
        vthi[dst] = hi;
        vtlo[dst] = lo;
    }
}

// ---------------- flash attention, split-KV partials (fixed-offset softmax) ------
#define FL_KSLO 17408
#define FL_VSHI 34816
#define FL_VSLO 53248
#define FL_STAGE 71680
#define FL_SMEM  143360

__global__ __launch_bounds__(256, 1)
void flash_kernel(const uint32_t* __restrict__ qhi, const uint32_t* __restrict__ qlo,
                  const uint32_t* __restrict__ khi, const uint32_t* __restrict__ klo,
                  const uint32_t* __restrict__ vthi, const uint32_t* __restrict__ vtlo,
                  float* __restrict__ part, float* __restrict__ lsum) {
    extern __shared__ char fsm[];
    const int tid = threadIdx.x;
    const int lane = tid & 31, warp = tid >> 5;
    const int g = lane >> 2, t4 = lane & 3;
    const int qt = blockIdx.x, bh = blockIdx.y, z = blockIdx.z;
    const int b = bh >> 4, h = bh & 15;
    const int wm = warp * 16;
    const long qr0 = (long)b * 2048 + qt * 128;

    part += (long)z * 4096 * 2048;
    lsum += (long)z * 4096 * 16;

    const uint32_t smem_base = (uint32_t)__cvta_generic_to_shared(fsm);

    uint32_t qah[8][4], qal[8][4];
    {
        const uint32_t* qh0 = qhi + (qr0 + wm + g) * 1024 + h * 64;
        const uint32_t* qh8 = qhi + (qr0 + wm + g + 8) * 1024 + h * 64;
        const uint32_t* ql0 = qlo + (qr0 + wm + g) * 1024 + h * 64;
        const uint32_t* ql8 = qlo + (qr0 + wm + g + 8) * 1024 + h * 64;
#pragma unroll
        for (int fs = 0; fs < 8; fs++) {
            qah[fs][0] = qh0[8 * fs + t4];
            qah[fs][1] = qh8[8 * fs + t4];
            qah[fs][2] = qh0[8 * fs + 4 + t4];
            qah[fs][3] = qh8[8 * fs + 4 + t4];
            qal[fs][0] = ql0[8 * fs + t4];
            qal[fs][1] = ql8[8 * fs + t4];
            qal[fs][2] = ql0[8 * fs + 4 + t4];
            qal[fs][3] = ql8[8 * fs + 4 + t4];
        }
    }

    float acc_o[16][4];
#pragma unroll
    for (int nt = 0; nt < 16; nt++)
#pragma unroll
        for (int j = 0; j < 4; j++) acc_o[nt][j] = 0.f;
    float lrow[2] = {0.f, 0.f};

    const uint32_t* khb = khi + ((long)b * 2048) * 1024 + h * 64;
    const uint32_t* klb = klo + ((long)b * 2048) * 1024 + h * 64;
    const uint32_t* vhb = vthi + ((long)b * 2048 + h * 128) * 1024;
    const uint32_t* vlb = vtlo + ((long)b * 2048 + h * 128) * 1024;

    const int kb0 = z * 16, kb1 = kb0 + 16;

    auto prefetch = [&](int kb) {
        uint32_t sb = smem_base + (kb & 1) * FL_STAGE;
        const uint32_t* kh = khb + (long)kb * 64 * 1024;
        const uint32_t* kl = klb + (long)kb * 64 * 1024;
#pragma unroll
        for (int i = 0; i < 4; i++) {
            int c = tid + i * 256;
            int row = c >> 4, cc = (c & 15) * 4;
            cpa16(sb + (row * 68 + cc) * 4, kh + (long)row * 1024 + cc);
            cpa16(sb + FL_KSLO + (row * 68 + cc) * 4, kl + (long)row * 1024 + cc);
        }
#pragma unroll
        for (int i = 0; i < 4; i++) {
            int c = tid + i * 256;
            int col = c >> 3, ci = (c & 7) * 4;
            cpa16(sb + FL_VSHI + (col * 36 + ci) * 4, vhb + (long)col * 1024 + kb * 32 + ci);
            cpa16(sb + FL_VSLO + (col * 36 + ci) * 4, vlb + (long)col * 1024 + kb * 32 + ci);
        }
        asm volatile("cp.async.commit_group;\n" ::: "memory");
    };

    prefetch(kb0);

    for (int kb = kb0; kb < kb1; kb++) {
        if (kb + 1 < kb1) {
            prefetch(kb + 1);
            asm volatile("cp.async.wait_group 1;\n" ::: "memory");
        } else {
            asm volatile("cp.async.wait_group 0;\n" ::: "memory");
        }
        __syncthreads();

        const uint32_t* ksh = (const uint32_t*)(fsm + (kb & 1) * FL_STAGE);
        const uint32_t* ksl = (const uint32_t*)(fsm + (kb & 1) * FL_STAGE + FL_KSLO);
        const uint32_t* vsh = (const uint32_t*)(fsm + (kb & 1) * FL_STAGE + FL_VSHI);
        const uint32_t* vsl = (const uint32_t*)(fsm + (kb & 1) * FL_STAGE + FL_VSLO);

        // ---- S = Q @ K^T (scores in log2 units via QSCALE) ----
        float sacc[8][4];
#pragma unroll
        for (int nt = 0; nt < 8; nt++)
#pragma unroll
            for (int j = 0; j < 4; j++) sacc[nt][j] = 0.f;

#pragma unroll
        for (int fs = 0; fs < 8; fs++) {
            uint32_t kb0h[8], kb1h[8], kb0l[8], kb1l[8];
#pragma unroll
            for (int nt = 0; nt < 8; nt++) {
                int o = (nt * 8 + g) * 68 + fs * 8 + t4;
                kb0h[nt] = ksh[o];
                kb1h[nt] = ksh[o + 4];
                kb0l[nt] = ksl[o];
                kb1l[nt] = ksl[o + 4];
            }
#pragma unroll
            for (int nt = 0; nt < 8; nt++) {
                mma16816(sacc[nt], qah[fs][0], qah[fs][1], qah[fs][2], qah[fs][3], kb0h[nt], kb1h[nt]);
                mma16816(sacc[nt], qah[fs][0], qah[fs][1], qah[fs][2], qah[fs][3], kb0l[nt], kb1l[nt]);
                mma16816(sacc[nt], qal[fs][0], qal[fs][1], qal[fs][2], qal[fs][3], kb0h[nt], kb1h[nt]);
            }
        }

        // ---- fixed-offset softmax: p = 2^(s - SOFF) ----
#pragma unroll
        for (int r = 0; r < 2; r++) {
            float rs = 0.f;
#pragma unroll
            for (int nt = 0; nt < 8; nt++) {
                float p0 = fexp2(sacc[nt][2 * r] - SOFF);
                float p1 = fexp2(sacc[nt][2 * r + 1] - SOFF);
                sacc[nt][2 * r] = p0;
                sacc[nt][2 * r + 1] = p1;
                rs += p0 + p1;
            }
            rs += __shfl_xor_sync(0xffffffffu, rs, 1);
            rs += __shfl_xor_sync(0xffffffffu, rs, 2);
            lrow[r] += rs;
        }

        // ---- O += P @ V, 3-pass split ----
#pragma unroll
        for (int s = 0; s < 4; s++) {
            uint32_t ph[4], pl[4];
            {
                uint32_t h0, l0;
                split_pair(sacc[2 * s][0], sacc[2 * s][1], h0, l0);         ph[0] = h0; pl[0] = l0;
                split_pair(sacc[2 * s][2], sacc[2 * s][3], h0, l0);         ph[1] = h0; pl[1] = l0;
                split_pair(sacc[2 * s + 1][0], sacc[2 * s + 1][1], h0, l0); ph[2] = h0; pl[2] = l0;
                split_pair(sacc[2 * s + 1][2], sacc[2 * s + 1][3], h0, l0); ph[3] = h0; pl[3] = l0;
            }
#pragma unroll
            for (int nt = 0; nt < 16; nt++) {
                int o = (nt * 8 + g) * 36 + s * 8 + t4;
                uint32_t v0h = vsh[o], v1h = vsh[o + 4];
                uint32_t v0l = vsl[o], v1l = vsl[o + 4];
                mma16816(acc_o[nt], ph[0], ph[1], ph[2], ph[3], v0h, v1h);
                mma16816(acc_o[nt], pl[0], pl[1], pl[2], pl[3], v0h, v1h);
                mma16816(acc_o[nt], ph[0], ph[1], ph[2], ph[3], v0l, v1l);
            }
        }
        __syncthreads();
    }

    // ---- epilogue: store unnormalized partials + l sums ----
    float* p0 = part + (qr0 + wm + g) * 2048 + h * 128;
    float* p8 = part + (qr0 + wm + g + 8) * 2048 + h * 128;
#pragma unroll
    for (int nt = 0; nt < 16; nt++) {
        int col = nt * 8 + 2 * t4;
        *(float2*)(p0 + col) = make_float2(acc_o[nt][0], acc_o[nt][1]);
        *(float2*)(p8 + col) = make_float2(acc_o[nt][2], acc_o[nt][3]);
    }
    if (t4 == 0) {
        lsum[(qr0 + wm + g) * 16 + h] = lrow[0];
        lsum[(qr0 + wm + g + 8) * 16 + h] = lrow[1];
    }
}

// ---------------- combine partials -> normalized split-pair output ----------------
__global__ void combine_kernel(const float* __restrict__ part, const float* __restrict__ lsum,
                               uint32_t* __restrict__ ahi, uint32_t* __restrict__ alo) {
    int idx = blockIdx.x * 256 + threadIdx.x;   // over 4096*1024 pairs
    int row = idx >> 10, pp = idx & 1023;
    int h = pp >> 6;
    float l = lsum[row * 16 + h] + lsum[4096 * 16 + row * 16 + h];
    float inv = 1.f / l;
    float2 a = ((const float2*)part)[idx];
    float2 b = ((const float2*)(part + 4096 * 2048))[idx];
    uint32_t hi, lo;
    split_pair((a.x + b.x) * inv, (a.y + b.y) * inv, hi, lo);
    ahi[idx] = hi;
    alo[idx] = lo;
}

// ---------------- host orchestration ----------------------------------------------
extern "C" void kernel_launch(void* const* d_in, const int* in_sizes, int n_in,
                              void* d_out, int out_size) {
    const float* xq = (const float*)d_in[0];
    const float* xk = (const float*)d_in[1];
    const float* xv = (const float*)d_in[2];
    const float* WQ = (const float*)d_in[3];
    const float* WK = (const float*)d_in[4];
    const float* WV = (const float*)d_in[5];
    const float* WO = (const float*)d_in[6];
    const float* bQ = (const float*)d_in[7];
    const float* bK = (const float*)d_in[8];
    const float* bV = (const float*)d_in[9];
    const float* bO = (const float*)d_in[10];
    const float* qw = (const float*)d_in[11];
    const float* kw = (const float*)d_in[12];
    float* out = (float*)d_out;

    float *qb, *kb, *vb, *ct, *st, *part, *lsum;
    uint32_t *xqhi, *xqlo, *xkhi, *xklo, *xvhi, *xvlo;
    uint32_t *w0hi, *w0lo, *w1hi, *w1lo, *w2hi, *w2lo, *wohi, *wolo;
    uint32_t *qhi, *qlo, *khi, *klo, *vthi, *vtlo, *ahi, *alo;
    cudaGetSymbolAddress((void**)&qb, g_q);
    cudaGetSymbolAddress((void**)&kb, g_k);
    cudaGetSymbolAddress((void**)&vb, g_v);
    cudaGetSymbolAddress((void**)&ct, g_cos);
    cudaGetSymbolAddress((void**)&st, g_sin);
    cudaGetSymbolAddress((void**)&part, g_part);
    cudaGetSymbolAddress((void**)&lsum, g_lsum);
    cudaGetSymbolAddress((void**)&xqhi, g_xqhi);
    cudaGetSymbolAddress((void**)&xqlo, g_xqlo);
    cudaGetSymbolAddress((void**)&xkhi, g_xkhi);
    cudaGetSymbolAddress((void**)&xklo, g_xklo);
    cudaGetSymbolAddress((void**)&xvhi, g_xvhi);
    cudaGetSymbolAddress((void**)&xvlo, g_xvlo);
    cudaGetSymbolAddress((void**)&w0hi, g_w0hi);
    cudaGetSymbolAddress((void**)&w0lo, g_w0lo);
    cudaGetSymbolAddress((void**)&w1hi, g_w1hi);
    cudaGetSymbolAddress((void**)&w1lo, g_w1lo);
    cudaGetSymbolAddress((void**)&w2hi, g_w2hi);
    cudaGetSymbolAddress((void**)&w2lo, g_w2lo);
    cudaGetSymbolAddress((void**)&wohi, g_wohi);
    cudaGetSymbolAddress((void**)&wolo, g_wolo);
    cudaGetSymbolAddress((void**)&qhi, g_qhi);
    cudaGetSymbolAddress((void**)&qlo, g_qlo);
    cudaGetSymbolAddress((void**)&khi, g_khi);
    cudaGetSymbolAddress((void**)&klo, g_klo);
    cudaGetSymbolAddress((void**)&vthi, g_vthi);
    cudaGetSymbolAddress((void**)&vtlo, g_vtlo);
    cudaGetSymbolAddress((void**)&ahi, g_ahi);
    cudaGetSymbolAddress((void**)&alo, g_alo);

    cudaFuncSetAttribute(flash_kernel, cudaFuncAttributeMaxDynamicSharedMemorySize, FL_SMEM);
    cudaFuncSetAttribute(bgemm2_kernel<3>, cudaFuncAttributeMaxDynamicSharedMemorySize, G2_SMEM);
    cudaFuncSetAttribute(bgemm2_kernel<1>, cudaFuncAttributeMaxDynamicSharedMemorySize, G2_SMEM);

    rope_table_kernel<<<(2048 * 64 + 255) / 256, 256>>>(ct, st);

    // pre-split inputs + weights (batched launches)
    dim3 gS(16384, 1, 3);
    split_rows3_kernel<<<gS, 256>>>(xq, xk, xv, xqhi, xqlo, xkhi, xklo, xvhi, xvlo);
    dim3 gW(8192, 1, 3);
    wsplit3_kernel<<<gW, 256>>>(WQ, WK, WV, w0hi, w0lo, w1hi, w1lo, w2hi, w2lo);
    wosplit_kernel<<<8192, 256>>>(WO, wohi, wolo);

    // QKV projections: one batched launch
    dim3 gProj3(16, 32, 3);
    bgemm2_kernel<3><<<gProj3, 256, G2_SMEM>>>(
        xqhi, xqlo, w0hi, w0lo, qb, bQ,
        xkhi, xklo, w1hi, w1lo, kb, bK,
        xvhi, xvlo, w2hi, w2lo, vb, bV);

    // RMSNorm + RoPE + split (q scaled by QSCALE)
    dim3 gNR(BB * SS * HH, 2);
    norm_rope_split_kernel<<<gNR, 128>>>(qb, kb, qw, kw, ct, st, qhi, qlo, khi, klo);

    // V transpose + split
    dim3 gV(32, 32, 2);
    v_tsplit_kernel<<<gV, 256>>>(vb, vthi, vtlo);

    // flash attention: split-KV partials (z = KV half), then combine
    dim3 gF(16, 32, 2);
    flash_kernel<<<gF, 256, FL_SMEM>>>(qhi, qlo, khi, klo, vthi, vtlo, part, lsum);
    combine_kernel<<<16384, 256>>>(part, lsum, ahi, alo);

    // output projection
    dim3 gProj(16, 32, 1);
    bgemm2_kernel<1><<<gProj, 256, G2_SMEM>>>(
        ahi, alo, wohi, wolo, out, bO,
        nullptr, nullptr, nullptr, nullptr, nullptr, nullptr,
        nullptr, nullptr, nullptr, nullptr, nullptr, nullptr);
}